// round 5
// baseline (speedup 1.0000x reference)
#include <cuda_runtime.h>
#include <cuda_fp8.h>
#include <cstdint>
#include <cstddef>

// Problem dims (fixed)
#define MDIM 16384
#define KDIM 4096
#define NDIM 4096

// ---------------- device globals (scratch; no allocations allowed) ----------------
__device__ unsigned int g_amax_x;
__device__ unsigned int g_amax_w;
__device__ float g_sx, g_sw, g_inv;
// fp8 e4m3 storage, K-major, with k PERMUTED within each 16-element group:
// storage index s(l) = (l&1) | ((l&6)<<1) | ((l>>3)<<1)
__device__ __align__(16) unsigned char g_xq[67108864];   // [M,K] fp8 (x quantized)
__device__ __align__(16) unsigned char g_wq[16777216];   // [N,K] fp8 (w^T quantized)

__host__ __device__ __forceinline__ int kperm16(int l) {
    return (l & 1) | ((l & 6) << 1) | ((l >> 3) << 1);
}

// ---------------- GEMM config ----------------
#define BM 128
#define BN 128
#define KC 64                    // fp8 elements per K-chunk per stage
#define STAGES 3
#define ITERS (KDIM / KC)        // 64
#define ROWB 80                  // padded smem row stride (bytes) -> conflict-free LDS
#define A_BYTES (BM * ROWB)      // 10240
#define B_BYTES (BN * ROWB)      // 10240
#define STAGE_BYTES (A_BYTES + B_BYTES)          // 20480
#define SMEM_BYTES (STAGES * STAGE_BYTES)        // 61440

// ---------------- helpers ----------------
__device__ __forceinline__ uint32_t smem_u32(const void* p) {
    uint32_t a;
    asm("{ .reg .u64 t; cvta.to.shared.u64 t, %1; cvt.u32.u64 %0, t; }" : "=r"(a) : "l"(p));
    return a;
}
__device__ __forceinline__ void cp_async16(uint32_t sdst, const void* gsrc) {
    asm volatile("cp.async.cg.shared.global [%0], [%1], 16;" :: "r"(sdst), "l"(gsrc) : "memory");
}
__device__ __forceinline__ uint32_t lds32(uint32_t addr) {
    uint32_t v;
    asm volatile("ld.shared.b32 %0, [%1];" : "=r"(v) : "r"(addr));
    return v;
}
// fp8 pair -> half2 holding (true value * 2^-8), exact incl. denormals.
__device__ __forceinline__ uint32_t cvt_lo(uint32_t x) {   // bytes 0,1
    uint32_t s = __byte_perm(x, 0, 0x4140);
    return ((s << 8) & 0x80008000u) | ((s << 7) & 0x3F803F80u);
}
__device__ __forceinline__ uint32_t cvt_hi(uint32_t x) {   // bytes 2,3
    uint32_t s = __byte_perm(x, 0, 0x4342);
    return ((s << 8) & 0x80008000u) | ((s << 7) & 0x3F803F80u);
}
__device__ __forceinline__ void mma16816(float& c0, float& c1, float& c2, float& c3,
                                         uint32_t a0, uint32_t a1, uint32_t a2, uint32_t a3,
                                         uint32_t b0, uint32_t b1) {
    asm volatile(
        "mma.sync.aligned.m16n8k16.row.col.f32.f16.f16.f32 "
        "{%0,%1,%2,%3}, {%4,%5,%6,%7}, {%8,%9}, {%0,%1,%2,%3};"
        : "+f"(c0), "+f"(c1), "+f"(c2), "+f"(c3)
        : "r"(a0), "r"(a1), "r"(a2), "r"(a3), "r"(b0), "r"(b1));
}

// Load one stage: A tile 128x64B + B tile 128x64B, 16B chunks, padded rows.
__device__ __forceinline__ void load_stage(uint32_t sbase, const unsigned char* Ag,
                                           const unsigned char* Bg, int tid) {
    #pragma unroll
    for (int it = 0; it < 4; it++) {
        int c = tid + it * 256;           // 0..1023
        int isB = c >> 9;
        int cc = c & 511;
        int row = cc >> 2;
        int kg = cc & 3;
        uint32_t dst = sbase + (uint32_t)(isB ? A_BYTES : 0) + (uint32_t)(row * ROWB + kg * 16);
        const unsigned char* src = (isB ? Bg : Ag) + (size_t)row * KDIM + kg * 16;
        cp_async16(dst, src);
    }
}

// ---------------- GEMM kernel (fp8-in-smem, fp16 HMMA, fp32 accum) ----------------
__global__ void __launch_bounds__(256, 2) gemm_kernel(float* __restrict__ out) {
    extern __shared__ __align__(16) unsigned char smem[];
    const uint32_t sb = smem_u32(smem);
    const int tid = threadIdx.x;
    const int wid = tid >> 5;
    const int lid = tid & 31;
    const int wm = wid & 3;        // 0..3 -> 32-row slice
    const int wn = wid >> 2;       // 0..1 -> 64-col slice
    const int lrow = lid >> 2;     // 0..7
    const int lq = lid & 3;        // 0..3
    const int n0 = blockIdx.x * BN;
    const int m0 = blockIdx.y * BM;

    const unsigned char* Ag = g_xq + (size_t)m0 * KDIM;
    const unsigned char* Bg = g_wq + (size_t)n0 * KDIM;

    float acc[2][8][4];
    #pragma unroll
    for (int mf = 0; mf < 2; mf++)
        #pragma unroll
        for (int nf = 0; nf < 8; nf++)
            #pragma unroll
            for (int j = 0; j < 4; j++) acc[mf][nf][j] = 0.0f;

    // prologue: fill first STAGES-1 stages
    #pragma unroll
    for (int s = 0; s < STAGES - 1; s++) {
        load_stage(sb + s * STAGE_BYTES, Ag + s * KC, Bg + s * KC, tid);
        asm volatile("cp.async.commit_group;" ::: "memory");
    }

    for (int i = 0; i < ITERS; i++) {
        // issue load for chunk i+STAGES-1 into stage (i+STAGES-1)%STAGES
        if (i + STAGES - 1 < ITERS) {
            const int ls = (i + STAGES - 1) % STAGES;
            load_stage(sb + ls * STAGE_BYTES,
                       Ag + (size_t)(i + STAGES - 1) * KC,
                       Bg + (size_t)(i + STAGES - 1) * KC, tid);
            asm volatile("cp.async.commit_group;" ::: "memory");
            asm volatile("cp.async.wait_group %0;" :: "n"(STAGES - 1) : "memory");
        } else {
            asm volatile("cp.async.wait_group 0;" ::: "memory");
        }
        __syncthreads();

        const uint32_t sA = sb + (uint32_t)((i % STAGES) * STAGE_BYTES);
        const uint32_t sB = sA + A_BYTES;

        #pragma unroll
        for (int kg = 0; kg < 4; kg++) {
            uint32_t a[2][4];
            #pragma unroll
            for (int mf = 0; mf < 2; mf++) {
                uint32_t r0 = lds32(sA + (uint32_t)((wm * 32 + mf * 16 + lrow) * ROWB + kg * 16 + lq * 4));
                uint32_t r1 = lds32(sA + (uint32_t)((wm * 32 + mf * 16 + lrow + 8) * ROWB + kg * 16 + lq * 4));
                a[mf][0] = cvt_lo(r0);
                a[mf][2] = cvt_hi(r0);
                a[mf][1] = cvt_lo(r1);
                a[mf][3] = cvt_hi(r1);
            }
            #pragma unroll
            for (int nf = 0; nf < 8; nf++) {
                uint32_t r = lds32(sB + (uint32_t)((wn * 64 + nf * 8 + lrow) * ROWB + kg * 16 + lq * 4));
                uint32_t b0 = cvt_lo(r);
                uint32_t b1 = cvt_hi(r);
                #pragma unroll
                for (int mf = 0; mf < 2; mf++) {
                    mma16816(acc[mf][nf][0], acc[mf][nf][1], acc[mf][nf][2], acc[mf][nf][3],
                             a[mf][0], a[mf][1], a[mf][2], a[mf][3], b0, b1);
                }
            }
        }
        __syncthreads();
    }

    // epilogue: dequantize (undo 2^-16 operand scaling) and store
    const float sc = 65536.0f * g_inv;
    #pragma unroll
    for (int mf = 0; mf < 2; mf++) {
        #pragma unroll
        for (int nf = 0; nf < 8; nf++) {
            const int m = m0 + wm * 32 + mf * 16 + lrow;
            const int n = n0 + wn * 64 + nf * 8 + lq * 2;
            float2 v0 = make_float2(acc[mf][nf][0] * sc, acc[mf][nf][1] * sc);
            float2 v1 = make_float2(acc[mf][nf][2] * sc, acc[mf][nf][3] * sc);
            *reinterpret_cast<float2*>(out + (size_t)m * NDIM + n) = v0;
            *reinterpret_cast<float2*>(out + (size_t)(m + 8) * NDIM + n) = v1;
        }
    }
}

// ---------------- pre-pass kernels ----------------
__global__ void reset_kernel() {
    g_amax_x = 0u;
    g_amax_w = 0u;
}

__global__ void absmax_kernel(const float4* __restrict__ p, long n4, int which) {
    float m = 0.0f;
    const long stride = (long)gridDim.x * blockDim.x;
    for (long i = (long)blockIdx.x * blockDim.x + threadIdx.x; i < n4; i += stride) {
        float4 v = p[i];
        m = fmaxf(m, fmaxf(fmaxf(fabsf(v.x), fabsf(v.y)), fmaxf(fabsf(v.z), fabsf(v.w))));
    }
    #pragma unroll
    for (int o = 16; o > 0; o >>= 1) m = fmaxf(m, __shfl_xor_sync(0xFFFFFFFFu, m, o));
    if ((threadIdx.x & 31) == 0) {
        atomicMax(which ? &g_amax_w : &g_amax_x, __float_as_uint(m));
    }
}

__global__ void scales_kernel() {
    const float ax = __uint_as_float(g_amax_x);
    const float aw = __uint_as_float(g_amax_w);
    const float sx = 448.0f / ax;
    const float sw = 448.0f / aw;
    g_sx = sx;
    g_sw = sw;
    g_inv = 1.0f / (sx * sw);
}

__device__ __forceinline__ unsigned char q8(float v) {
    return (unsigned char)__nv_cvt_float_to_fp8(v, __NV_SATFINITE, __NV_E4M3);
}

// quantize x: one thread handles one 16-element k-group, writes permuted uint4
__global__ void quant_x_kernel(const float4* __restrict__ x, long ngroups) {
    const float sx = g_sx;
    uint4* __restrict__ outv = reinterpret_cast<uint4*>(g_xq);
    const long stride = (long)gridDim.x * blockDim.x;
    for (long g = (long)blockIdx.x * blockDim.x + threadIdx.x; g < ngroups; g += stride) {
        uint32_t w[4] = {0u, 0u, 0u, 0u};
        #pragma unroll
        for (int j = 0; j < 4; j++) {
            float4 v = x[g * 4 + j];
            float e[4] = {v.x, v.y, v.z, v.w};
            #pragma unroll
            for (int t = 0; t < 4; t++) {
                int l = j * 4 + t;
                int s = kperm16(l);
                w[s >> 2] |= (uint32_t)q8(e[t] * sx) << ((s & 3) * 8);
            }
        }
        outv[g] = make_uint4(w[0], w[1], w[2], w[3]);
    }
}

// quantize + transpose w: wq[n*K + perm(k)] = q(w[k*N + n] * sw)
__global__ void quant_w_kernel(const float* __restrict__ w) {
    __shared__ unsigned char t[32][33];
    const int n0 = blockIdx.x * 32;
    const int k0 = blockIdx.y * 32;
    const float sw = g_sw;
    const int tx = threadIdx.x;  // 0..31
    const int ty = threadIdx.y;  // 0..7
    #pragma unroll
    for (int i = 0; i < 4; i++) {
        const int kk = ty + i * 8;
        const float v = w[(size_t)(k0 + kk) * NDIM + n0 + tx];
        t[kk][tx] = q8(v * sw);
    }
    __syncthreads();
    const int kp = (tx & 16) | kperm16(tx & 15);
    #pragma unroll
    for (int i = 0; i < 4; i++) {
        const int nn = ty + i * 8;
        g_wq[(size_t)(n0 + nn) * KDIM + k0 + kp] = t[tx][nn];
    }
}

// ---------------- launcher ----------------
extern "C" void kernel_launch(void* const* d_in, const int* in_sizes, int n_in,
                              void* d_out, int out_size) {
    const float* x = (const float*)d_in[0];   // [M,K]
    const float* w = (const float*)d_in[1];   // [K,N]
    float* out = (float*)d_out;               // [M,N]

    reset_kernel<<<1, 1>>>();
    absmax_kernel<<<2048, 256>>>((const float4*)x, (long)MDIM * KDIM / 4, 0);
    absmax_kernel<<<1024, 256>>>((const float4*)w, (long)KDIM * NDIM / 4, 1);
    scales_kernel<<<1, 1>>>();
    quant_x_kernel<<<4096, 256>>>((const float4*)x, (long)MDIM * KDIM / 16);
    quant_w_kernel<<<dim3(NDIM / 32, KDIM / 32), dim3(32, 8)>>>(w);

    cudaFuncSetAttribute(gemm_kernel, cudaFuncAttributeMaxDynamicSharedMemorySize, SMEM_BYTES);
    gemm_kernel<<<dim3(NDIM / BN, MDIM / BM), 256, SMEM_BYTES>>>(out);
}

// round 10
// speedup vs baseline: 1.3153x; 1.3153x over previous
#include <cuda_runtime.h>
#include <cuda_fp8.h>
#include <cstdint>
#include <cstddef>

// Problem dims (fixed)
#define MDIM 16384
#define KDIM 4096
#define NDIM 4096

// ---------------- device globals (scratch; no allocations allowed) ----------------
__device__ unsigned int g_amax_x;
__device__ unsigned int g_amax_w;
__device__ float g_sx, g_sw, g_inv;
__device__ __align__(16) unsigned char g_xq[67108864];   // [M,K] fp8 e4m3, K-major
__device__ __align__(16) unsigned char g_wq[16777216];   // [N,K] fp8 e4m3, K-major (w^T)

// ---------------- GEMM config ----------------
#define BM 256
#define BN 128
#define KC 128                   // fp8 elements (bytes) of K per stage; 128B rows = SW128 native
#define STAGES 3
#define ITERS (KDIM / KC)        // 32
#define A_BYTES (BM * 128)       // 32768
#define B_BYTES (BN * 128)       // 16384
#define STAGE_BYTES (A_BYTES + B_BYTES)     // 49152
#define SMEM_BYTES (STAGES * STAGE_BYTES)   // 147456

// ---------------- helpers ----------------
__device__ __forceinline__ uint32_t smem_u32(const void* p) {
    uint32_t a;
    asm("{ .reg .u64 t; cvta.to.shared.u64 t, %1; cvt.u32.u64 %0, t; }" : "=r"(a) : "l"(p));
    return a;
}
__device__ __forceinline__ void cp_async16(uint32_t sdst, const void* gsrc) {
    asm volatile("cp.async.cg.shared.global [%0], [%1], 16;" :: "r"(sdst), "l"(gsrc) : "memory");
}
__device__ __forceinline__ void ldsm4(uint32_t& r0, uint32_t& r1, uint32_t& r2, uint32_t& r3,
                                      uint32_t addr) {
    asm volatile("ldmatrix.sync.aligned.m8n8.x4.shared.b16 {%0,%1,%2,%3}, [%4];"
                 : "=r"(r0), "=r"(r1), "=r"(r2), "=r"(r3) : "r"(addr));
}
// fp8 e4m3 MMA: D(f32) += A(e4m3) * B(e4m3), m16n8k32
__device__ __forceinline__ void mma_fp8(float& c0, float& c1, float& c2, float& c3,
                                        uint32_t a0, uint32_t a1, uint32_t a2, uint32_t a3,
                                        uint32_t b0, uint32_t b1) {
    asm volatile(
        "mma.sync.aligned.m16n8k32.row.col.f32.e4m3.e4m3.f32 "
        "{%0,%1,%2,%3}, {%4,%5,%6,%7}, {%8,%9}, {%0,%1,%2,%3};"
        : "+f"(c0), "+f"(c1), "+f"(c2), "+f"(c3)
        : "r"(a0), "r"(a1), "r"(a2), "r"(a3), "r"(b0), "r"(b1));
}

// SW128-style swizzle for 128B rows: XOR (row&7) into the 16B-chunk index.
__device__ __forceinline__ uint32_t swz(uint32_t off) {
    return off ^ ((off >> 3) & 0x70u);
}

// Load one stage: A tile 256x128B + B tile 128x128B, 16B cp.async chunks.
__device__ __forceinline__ void load_stage(uint32_t sbase, const unsigned char* Ag,
                                           const unsigned char* Bg, int tid) {
    #pragma unroll
    for (int it = 0; it < 6; it++) {
        int c = tid + it * 512;            // 0..3071
        int isB = (c >= 2048);
        int cc = isB ? (c - 2048) : c;
        int row = cc >> 3;
        int chunk = cc & 7;
        uint32_t off = (uint32_t)(row * 128 + chunk * 16);
        uint32_t dst = sbase + (uint32_t)(isB ? A_BYTES : 0) + swz(off);
        const unsigned char* src = (isB ? Bg : Ag) + (size_t)row * KDIM + chunk * 16;
        cp_async16(dst, src);
    }
}

// ---------------- GEMM kernel (fp8 smem, native fp8 mma.sync, fp32 accum) ----------------
__global__ void __launch_bounds__(512, 1) gemm_kernel(float* __restrict__ out) {
    extern __shared__ __align__(16) unsigned char smem[];
    const uint32_t sb = smem_u32(smem);
    const int tid = threadIdx.x;
    const int wid = tid >> 5;
    const int lid = tid & 31;
    const int wn = wid & 3;        // 0..3 -> 32-col slice
    const int wm = wid >> 2;       // 0..3 -> 64-row slice
    const int n0 = blockIdx.x * BN;
    const int m0 = blockIdx.y * BM;

    const unsigned char* Ag = g_xq + (size_t)m0 * KDIM;
    const unsigned char* Bg = g_wq + (size_t)n0 * KDIM;

    float acc[4][4][4];            // [mf 16-row][nf 8-col][frag]
    #pragma unroll
    for (int mf = 0; mf < 4; mf++)
        #pragma unroll
        for (int nf = 0; nf < 4; nf++)
            #pragma unroll
            for (int j = 0; j < 4; j++) acc[mf][nf][j] = 0.0f;

    // Per-lane ldmatrix row offsets (row*128 with swizzle mask folded per kk below).
    // A: x4 matrices ordered [m0-7,klo][m8-15,klo][m0-7,khi][m8-15,khi]:
    //    lane i -> row = mf*16 + (i&15), chunk-half = i>>4
    const int a_row_in = lid & 15;
    const int a_ci = lid >> 4;           // 0/1
    // B: x4 matrices ordered [n0-7,klo][n0-7,khi][n8-15,klo][n8-15,khi]:
    //    lane i -> matrix j=i>>3, l=i&7: row = nf2*16 + (j>>1)*8 + l, chunk-half = j&1
    const int b_row_in = ((lid >> 4) << 3) + (lid & 7);
    const int b_ci = (lid >> 3) & 1;

    // prologue
    #pragma unroll
    for (int s = 0; s < STAGES - 1; s++) {
        load_stage(sb + s * STAGE_BYTES, Ag + s * KC, Bg + s * KC, tid);
        asm volatile("cp.async.commit_group;" ::: "memory");
    }

    for (int i = 0; i < ITERS; i++) {
        if (i + STAGES - 1 < ITERS) {
            const int ls = (i + STAGES - 1) % STAGES;
            load_stage(sb + ls * STAGE_BYTES,
                       Ag + (size_t)(i + STAGES - 1) * KC,
                       Bg + (size_t)(i + STAGES - 1) * KC, tid);
            asm volatile("cp.async.commit_group;" ::: "memory");
            asm volatile("cp.async.wait_group %0;" :: "n"(STAGES - 1) : "memory");
        } else {
            asm volatile("cp.async.wait_group 0;" ::: "memory");
        }
        __syncthreads();

        const uint32_t sA = sb + (uint32_t)((i % STAGES) * STAGE_BYTES);
        const uint32_t sB = sA + A_BYTES;

        #pragma unroll
        for (int kk = 0; kk < 4; kk++) {   // 4 x k32 steps cover KC=128
            uint32_t a[4][4];
            #pragma unroll
            for (int mf = 0; mf < 4; mf++) {
                const int row = wm * 64 + mf * 16 + a_row_in;
                const uint32_t off = (uint32_t)(row * 128 + (kk * 2 + a_ci) * 16);
                ldsm4(a[mf][0], a[mf][1], a[mf][2], a[mf][3], sA + swz(off));
            }
            uint32_t b[4][2];
            #pragma unroll
            for (int nf2 = 0; nf2 < 2; nf2++) {
                const int row = wn * 32 + nf2 * 16 + b_row_in;
                const uint32_t off = (uint32_t)(row * 128 + (kk * 2 + b_ci) * 16);
                uint32_t r0, r1, r2, r3;
                ldsm4(r0, r1, r2, r3, sB + swz(off));
                b[nf2 * 2 + 0][0] = r0; b[nf2 * 2 + 0][1] = r1;
                b[nf2 * 2 + 1][0] = r2; b[nf2 * 2 + 1][1] = r3;
            }
            #pragma unroll
            for (int mf = 0; mf < 4; mf++)
                #pragma unroll
                for (int nf = 0; nf < 4; nf++)
                    mma_fp8(acc[mf][nf][0], acc[mf][nf][1], acc[mf][nf][2], acc[mf][nf][3],
                            a[mf][0], a[mf][1], a[mf][2], a[mf][3],
                            b[nf][0], b[nf][1]);
        }
        __syncthreads();
    }

    // epilogue: dequantize and store
    const float sc = g_inv;
    const int lrow = lid >> 2;
    const int lq = lid & 3;
    #pragma unroll
    for (int mf = 0; mf < 4; mf++) {
        #pragma unroll
        for (int nf = 0; nf < 4; nf++) {
            const int m = m0 + wm * 64 + mf * 16 + lrow;
            const int n = n0 + wn * 32 + nf * 8 + lq * 2;
            float2 v0 = make_float2(acc[mf][nf][0] * sc, acc[mf][nf][1] * sc);
            float2 v1 = make_float2(acc[mf][nf][2] * sc, acc[mf][nf][3] * sc);
            *reinterpret_cast<float2*>(out + (size_t)m * NDIM + n) = v0;
            *reinterpret_cast<float2*>(out + (size_t)(m + 8) * NDIM + n) = v1;
        }
    }
}

// ---------------- pre-pass kernels ----------------
__global__ void reset_kernel() {
    g_amax_x = 0u;
    g_amax_w = 0u;
}

__global__ void absmax_kernel(const float4* __restrict__ p, long n4, int which) {
    float m = 0.0f;
    const long stride = (long)gridDim.x * blockDim.x;
    for (long i = (long)blockIdx.x * blockDim.x + threadIdx.x; i < n4; i += stride) {
        float4 v = p[i];
        m = fmaxf(m, fmaxf(fmaxf(fabsf(v.x), fabsf(v.y)), fmaxf(fabsf(v.z), fabsf(v.w))));
    }
    #pragma unroll
    for (int o = 16; o > 0; o >>= 1) m = fmaxf(m, __shfl_xor_sync(0xFFFFFFFFu, m, o));
    if ((threadIdx.x & 31) == 0) {
        atomicMax(which ? &g_amax_w : &g_amax_x, __float_as_uint(m));
    }
}

__global__ void scales_kernel() {
    const float ax = __uint_as_float(g_amax_x);
    const float aw = __uint_as_float(g_amax_w);
    const float sx = 448.0f / ax;
    const float sw = 448.0f / aw;
    g_sx = sx;
    g_sw = sw;
    g_inv = 1.0f / (sx * sw);
}

__device__ __forceinline__ unsigned char q8(float v) {
    return (unsigned char)__nv_cvt_float_to_fp8(v, __NV_SATFINITE, __NV_E4M3);
}

// quantize x: 4 fp32 -> packed 4x fp8 per thread-iteration
__global__ void quant_x_kernel(const float4* __restrict__ x, long n4) {
    const float sx = g_sx;
    uint32_t* __restrict__ outw = reinterpret_cast<uint32_t*>(g_xq);
    const long stride = (long)gridDim.x * blockDim.x;
    for (long i = (long)blockIdx.x * blockDim.x + threadIdx.x; i < n4; i += stride) {
        float4 v = x[i];
        uint32_t o = (uint32_t)q8(v.x * sx)
                   | ((uint32_t)q8(v.y * sx) << 8)
                   | ((uint32_t)q8(v.z * sx) << 16)
                   | ((uint32_t)q8(v.w * sx) << 24);
        outw[i] = o;
    }
}

// quantize + transpose w: wq[n*K + k] = q(w[k*N + n] * sw)
__global__ void quant_w_kernel(const float* __restrict__ w) {
    __shared__ unsigned char t[32][33];
    const int n0 = blockIdx.x * 32;
    const int k0 = blockIdx.y * 32;
    const float sw = g_sw;
    const int tx = threadIdx.x;  // 0..31
    const int ty = threadIdx.y;  // 0..7
    #pragma unroll
    for (int i = 0; i < 4; i++) {
        const int kk = ty + i * 8;
        const float v = w[(size_t)(k0 + kk) * NDIM + n0 + tx];
        t[kk][tx] = q8(v * sw);
    }
    __syncthreads();
    #pragma unroll
    for (int i = 0; i < 4; i++) {
        const int nn = ty + i * 8;
        g_wq[(size_t)(n0 + nn) * KDIM + k0 + tx] = t[tx][nn];
    }
}

// ---------------- launcher ----------------
extern "C" void kernel_launch(void* const* d_in, const int* in_sizes, int n_in,
                              void* d_out, int out_size) {
    const float* x = (const float*)d_in[0];   // [M,K]
    const float* w = (const float*)d_in[1];   // [K,N]
    float* out = (float*)d_out;               // [M,N]

    reset_kernel<<<1, 1>>>();
    absmax_kernel<<<2048, 256>>>((const float4*)x, (long)MDIM * KDIM / 4, 0);
    absmax_kernel<<<1024, 256>>>((const float4*)w, (long)KDIM * NDIM / 4, 1);
    scales_kernel<<<1, 1>>>();
    quant_x_kernel<<<4096, 256>>>((const float4*)x, (long)MDIM * KDIM / 4);
    quant_w_kernel<<<dim3(NDIM / 32, KDIM / 32), dim3(32, 8)>>>(w);

    cudaFuncSetAttribute(gemm_kernel, cudaFuncAttributeMaxDynamicSharedMemorySize, SMEM_BYTES);
    gemm_kernel<<<dim3(NDIM / BN, MDIM / BM), 512, SMEM_BYTES>>>(out);
}